// round 6
// baseline (speedup 1.0000x reference)
#include <cuda_runtime.h>
#include <math.h>

// Problem constants (fixed by the dataset).
#define N_MAX 50000
#define E_MAX 800000

// -------- scratch (static device globals; no runtime allocation) --------
__device__ float    g_q[N_MAX * 128];
__device__ float    g_k[N_MAX * 128];
__device__ float    g_v[N_MAX * 128];
__device__ float    g_skip[N_MAX * 128];
__device__ float    g_res[N_MAX * 128];
__device__ float    g_qe[N_MAX * 64];
__device__ float    g_s[N_MAX * 64];     // sagg
__device__ float    g_aggV[N_MAX * 128]; // unnormalized Σ ex*v
__device__ float    g_gate[N_MAX];
__device__ float    g_denom[N_MAX];
// CSR build scratch
__device__ int      g_cnt[N_MAX];
__device__ int      g_rowptr[N_MAX + 1];
__device__ int      g_wptr[N_MAX];
__device__ int2     g_srt[E_MAX];        // (src, edge_id) sorted by dst
__device__ int      g_dsts[E_MAX];       // dst per sorted position
__device__ float    g_exs[E_MAX];        // ex per sorted position

// ---------------------------------------------------------------------------
// tf32 split: x = hi + lo, both tf32-formatted (usable directly by mma).
// ---------------------------------------------------------------------------
__device__ __forceinline__ float2 tf32_split(float xf) {
    unsigned hi;
    asm("cvt.rna.tf32.f32 %0, %1;" : "=r"(hi) : "f"(xf));
    float lo = xf - __uint_as_float(hi);
    unsigned lob;
    asm("cvt.rna.tf32.f32 %0, %1;" : "=r"(lob) : "f"(lo));
    return make_float2(__uint_as_float(hi), __uint_as_float(lob));
}

__device__ __forceinline__ void mma_tf32(float c[4], const unsigned a[4], const unsigned b[2]) {
    asm volatile(
        "mma.sync.aligned.m16n8k8.row.col.f32.tf32.tf32.f32 "
        "{%0,%1,%2,%3}, {%4,%5,%6,%7}, {%8,%9}, {%0,%1,%2,%3};"
        : "+f"(c[0]), "+f"(c[1]), "+f"(c[2]), "+f"(c[3])
        : "r"(a[0]), "r"(a[1]), "r"(a[2]), "r"(a[3]), "r"(b[0]), "r"(b[1]));
}

// ---------------------------------------------------------------------------
// Node linear via tf32x3 tensor-core MMA (5 weight sets via gridDim.y).
// ---------------------------------------------------------------------------
#define SA_STRIDE 36
#define SB_STRIDE 130
__global__ __launch_bounds__(256) void mma_linear5_kernel(
    const float* __restrict__ x,
    const float* __restrict__ Wq, const float* __restrict__ bq, float* __restrict__ oq,
    const float* __restrict__ Wk, const float* __restrict__ bk, float* __restrict__ ok,
    const float* __restrict__ Wv, const float* __restrict__ bv, float* __restrict__ ov,
    const float* __restrict__ Ws, const float* __restrict__ bs, float* __restrict__ os,
    const float* __restrict__ Wr, const float* __restrict__ br, float* __restrict__ orr,
    int n) {
    extern __shared__ float2 dyn[];
    float2* sA = dyn;                     // 64*36
    float2* sB = dyn + 64 * SA_STRIDE;    // 32*130

    const float* W; const float* b; float* out;
    switch (blockIdx.y) {
        case 0: W = Wq; b = bq; out = oq; break;
        case 1: W = Wk; b = bk; out = ok; break;
        case 2: W = Wv; b = bv; out = ov; break;
        case 3: W = Ws; b = bs; out = os; break;
        default: W = Wr; b = br; out = orr; break;
    }

    const int tid = threadIdx.x;
    const int wid = tid >> 5, lane = tid & 31;
    const int g = lane >> 2, t4 = lane & 3;
    const int wm = (wid & 1) * 32;
    const int wn = (wid >> 1) * 32;
    const int base = blockIdx.x * 64;

    float acc[2][4][4];
#pragma unroll
    for (int mi = 0; mi < 2; mi++)
#pragma unroll
        for (int ni = 0; ni < 4; ni++)
#pragma unroll
            for (int r = 0; r < 4; r++) acc[mi][ni][r] = 0.f;

    for (int kc = 0; kc < 4; kc++) {
#pragma unroll
        for (int t = 0; t < 2; t++) {
            int i = tid + t * 256;
            int row = i >> 3;
            int c4 = i & 7;
            int gr = base + row; if (gr >= n) gr = n - 1;
            const float4 xv = *(const float4*)(x + (size_t)gr * 128 + kc * 32 + c4 * 4);
            float2* dp = sA + row * SA_STRIDE + c4 * 4;
            dp[0] = tf32_split(xv.x);
            dp[1] = tf32_split(xv.y);
            dp[2] = tf32_split(xv.z);
            dp[3] = tf32_split(xv.w);
        }
#pragma unroll
        for (int t = 0; t < 4; t++) {
            int i = tid + t * 256;
            int row = i >> 5;
            int c4 = i & 31;
            const float4 wv = *(const float4*)(W + (size_t)(kc * 32 + row) * 128 + c4 * 4);
            float2* dp = sB + row * SB_STRIDE + c4 * 4;
            dp[0] = tf32_split(wv.x);
            dp[1] = tf32_split(wv.y);
            dp[2] = tf32_split(wv.z);
            dp[3] = tf32_split(wv.w);
        }
        __syncthreads();

#pragma unroll
        for (int k8 = 0; k8 < 4; k8++) {
            const int kk = k8 * 8;
            unsigned Ahi[2][4], Alo[2][4];
#pragma unroll
            for (int mi = 0; mi < 2; mi++) {
                const int r0 = wm + mi * 16 + g;
                const float2 a00 = sA[r0 * SA_STRIDE + kk + t4];
                const float2 a10 = sA[(r0 + 8) * SA_STRIDE + kk + t4];
                const float2 a01 = sA[r0 * SA_STRIDE + kk + t4 + 4];
                const float2 a11 = sA[(r0 + 8) * SA_STRIDE + kk + t4 + 4];
                Ahi[mi][0] = __float_as_uint(a00.x); Alo[mi][0] = __float_as_uint(a00.y);
                Ahi[mi][1] = __float_as_uint(a10.x); Alo[mi][1] = __float_as_uint(a10.y);
                Ahi[mi][2] = __float_as_uint(a01.x); Alo[mi][2] = __float_as_uint(a01.y);
                Ahi[mi][3] = __float_as_uint(a11.x); Alo[mi][3] = __float_as_uint(a11.y);
            }
            unsigned Bhi[4][2], Blo[4][2];
#pragma unroll
            for (int ni = 0; ni < 4; ni++) {
                const int col = wn + ni * 8 + g;
                const float2 b0 = sB[(kk + t4) * SB_STRIDE + col];
                const float2 b1 = sB[(kk + t4 + 4) * SB_STRIDE + col];
                Bhi[ni][0] = __float_as_uint(b0.x); Blo[ni][0] = __float_as_uint(b0.y);
                Bhi[ni][1] = __float_as_uint(b1.x); Blo[ni][1] = __float_as_uint(b1.y);
            }
#pragma unroll
            for (int mi = 0; mi < 2; mi++)
#pragma unroll
                for (int ni = 0; ni < 4; ni++) {
                    mma_tf32(acc[mi][ni], Ahi[mi], Bhi[ni]);
                    mma_tf32(acc[mi][ni], Ahi[mi], Blo[ni]);
                    mma_tf32(acc[mi][ni], Alo[mi], Bhi[ni]);
                }
        }
        __syncthreads();
    }

#pragma unroll
    for (int ni = 0; ni < 4; ni++) {
        const int col = wn + ni * 8 + 2 * t4;
        const float2 bb = *(const float2*)(b + col);
#pragma unroll
        for (int mi = 0; mi < 2; mi++) {
            const int node0 = base + wm + mi * 16 + g;
            if (node0 < n) {
                float2 o0 = make_float2(acc[mi][ni][0] + bb.x, acc[mi][ni][1] + bb.y);
                *(float2*)(out + (size_t)node0 * 128 + col) = o0;
            }
            const int node1 = node0 + 8;
            if (node1 < n) {
                float2 o1 = make_float2(acc[mi][ni][2] + bb.x, acc[mi][ni][3] + bb.y);
                *(float2*)(out + (size_t)node1 * 128 + col) = o1;
            }
        }
    }
}

// ---------------------------------------------------------------------------
// qe[n][d] = sum_c q[n][c] * We[d][c]   (128 -> 64)
// ---------------------------------------------------------------------------
__global__ void qe_kernel(const float* __restrict__ q, const float* __restrict__ We,
                          float* __restrict__ qe, int n) {
    __shared__ float sWeT[128 * 64];
    __shared__ float sq[16 * 128];
    const int tid = threadIdx.x;       // 128
    for (int i = tid; i < 64 * 128; i += 128) {
        int d = i >> 7, c = i & 127;
        sWeT[c * 64 + d] = We[i];
    }
    __syncthreads();
    const int cg = tid & 15;
    const int ng = tid >> 4;

    for (int base = blockIdx.x * 16; base < n; base += gridDim.x * 16) {
        const int cnt = min(16, n - base);
        __syncthreads();
        for (int i = tid; i < cnt * 128; i += 128) sq[i] = q[(size_t)base * 128 + i];
        __syncthreads();

        float acc[2][4] = {{0.f, 0.f, 0.f, 0.f}, {0.f, 0.f, 0.f, 0.f}};
#pragma unroll 2
        for (int c = 0; c < 128; c++) {
            const float4 w = *((const float4*)(sWeT + c * 64) + cg);
#pragma unroll
            for (int j = 0; j < 2; j++) {
                float xv = sq[(ng * 2 + j) * 128 + c];
                acc[j][0] = fmaf(xv, w.x, acc[j][0]);
                acc[j][1] = fmaf(xv, w.y, acc[j][1]);
                acc[j][2] = fmaf(xv, w.z, acc[j][2]);
                acc[j][3] = fmaf(xv, w.w, acc[j][3]);
            }
        }
#pragma unroll
        for (int j = 0; j < 2; j++) {
            const int node = ng * 2 + j;
            if (node < cnt) {
                float4 o = make_float4(acc[j][0], acc[j][1], acc[j][2], acc[j][3]);
                ((float4*)(qe + (size_t)(base + node) * 64))[cg] = o;
            }
        }
    }
}

// ---------------------------------------------------------------------------
// gate[n] = sigmoid(x[n] . Wg + bg)
// ---------------------------------------------------------------------------
__global__ void gate_kernel(const float* __restrict__ x, const float* __restrict__ Wg,
                            const float* __restrict__ bg, float* __restrict__ gate, int n) {
    const int node = blockIdx.x * (blockDim.x >> 5) + (threadIdx.x >> 5);
    const int lane = threadIdx.x & 31;
    if (node >= n) return;
    const float4 a = ((const float4*)(x + (size_t)node * 128))[lane];
    const float4 w = ((const float4*)Wg)[lane];
    float s = a.x * w.x + a.y * w.y + a.z * w.z + a.w * w.w;
#pragma unroll
    for (int o = 16; o > 0; o >>= 1) s += __shfl_xor_sync(0xffffffffu, s, o);
    if (lane == 0) gate[node] = 1.f / (1.f + expf(-(s + bg[0])));
}

// ---------------------------------------------------------------------------
// CSR build: zero -> histogram -> scan -> scatter
// ---------------------------------------------------------------------------
__global__ void zero_cnt_kernel(int* __restrict__ cnt, int n) {
    const int i = blockIdx.x * blockDim.x + threadIdx.x;
    if (i < n) cnt[i] = 0;
}

__global__ void hist_kernel(const int* __restrict__ dstp, int* __restrict__ cnt, int ecnt) {
    const int i = blockIdx.x * blockDim.x + threadIdx.x;
    if (i < ecnt) atomicAdd(&cnt[dstp[i]], 1);
}

#define SCAN_T 1024
__global__ void scan_kernel(const int* __restrict__ cnt, int* __restrict__ rowptr,
                            int* __restrict__ wptr, int n) {
    __shared__ int sp[SCAN_T];
    const int tid = threadIdx.x;
    const int chunk = (n + SCAN_T - 1) / SCAN_T;
    const int s = tid * chunk;
    const int e = min(s + chunk, n);
    int sum = 0;
    for (int i = s; i < e; i++) sum += cnt[i];
    sp[tid] = sum;
    __syncthreads();
    for (int o = 1; o < SCAN_T; o <<= 1) {
        int vpr = (tid >= o) ? sp[tid - o] : 0;
        __syncthreads();
        sp[tid] += vpr;
        __syncthreads();
    }
    int run = (tid > 0) ? sp[tid - 1] : 0;
    for (int i = s; i < e; i++) {
        rowptr[i] = run;
        wptr[i] = run;
        run += cnt[i];
    }
    if (tid == SCAN_T - 1) rowptr[n] = sp[SCAN_T - 1];
}

__global__ void scatter_kernel(const int* __restrict__ ei, int* __restrict__ wptr,
                               int2* __restrict__ srt, int* __restrict__ dsts, int ecnt) {
    const int e = blockIdx.x * blockDim.x + threadIdx.x;
    if (e >= ecnt) return;
    const int dst = ei[ecnt + e];
    const int pos = atomicAdd(&wptr[dst], 1);
    srt[pos] = make_int2(ei[e], e);
    dsts[pos] = dst;
}

// ---------------------------------------------------------------------------
// Score pass (edge-parallel over SORTED positions, atomic-free):
//   exs[p] = __expf((q[dst].k[src] + qe[dst].ea_e)/sqrt(128))
// One warp per sorted position; consecutive p share dst -> q/qe L1 hits.
// ---------------------------------------------------------------------------
__global__ __launch_bounds__(256) void score_kernel(
    const int2* __restrict__ srt, const int* __restrict__ dsts,
    const float* __restrict__ ea, const float* __restrict__ q,
    const float* __restrict__ k, const float* __restrict__ qe,
    float* __restrict__ exs, int ecnt) {
    const int p = blockIdx.x * (blockDim.x >> 5) + (threadIdx.x >> 5);
    const int lane = threadIdx.x & 31;
    if (p >= ecnt) return;
    const int2 se = __ldg(&srt[p]);
    const int dst = __ldg(&dsts[p]);
    const float4 a  = ((const float4*)(q + (size_t)dst * 128))[lane];
    const float4 bb = ((const float4*)(k + (size_t)se.x * 128))[lane];
    float s = a.x * bb.x + a.y * bb.y + a.z * bb.z + a.w * bb.w;
    const float2 c = ((const float2*)(qe + (size_t)dst * 64))[lane];
    const float2 d = ((const float2*)(ea + (size_t)se.y * 64))[lane];
    s += c.x * d.x + c.y * d.y;
#pragma unroll
    for (int o = 16; o > 0; o >>= 1) s += __shfl_xor_sync(0xffffffffu, s, o);
    if (lane == 0) exs[p] = __expf(s * 0.08838834764831845f);   // 1/sqrt(128)
}

// ---------------------------------------------------------------------------
// Aggregation pass (CSR, warp per node, broadcast-style — no shfl reductions):
//   acc += ex*v[src]; sacc += ex*ea_e; den += ex.  Single store per node.
// Lanes batch-load 32 edge records, then broadcast one edge at a time.
// ---------------------------------------------------------------------------
__global__ __launch_bounds__(256) void agg2_kernel(
    const int* __restrict__ rowptr, const int2* __restrict__ srt,
    const float* __restrict__ exs, const float* __restrict__ ea,
    const float* __restrict__ v, float* __restrict__ aggV,
    float* __restrict__ sagg, float* __restrict__ denom, int n) {
    const int node = blockIdx.x * (blockDim.x >> 5) + (threadIdx.x >> 5);
    const int lane = threadIdx.x & 31;
    if (node >= n) return;
    const int beg = rowptr[node];
    const int end = rowptr[node + 1];

    float4 acc  = make_float4(0.f, 0.f, 0.f, 0.f);
    float2 sacc = make_float2(0.f, 0.f);
    float  den  = 0.f;

    for (int p0 = beg; p0 < end; p0 += 32) {
        const int cnt = min(32, end - p0);
        int2 se = make_int2(0, 0);
        float exl = 0.f;
        if (lane < cnt) {
            se  = __ldg(&srt[p0 + lane]);
            exl = __ldg(&exs[p0 + lane]);
        }
#pragma unroll 4
        for (int j = 0; j < cnt; j++) {
            const int   srcj = __shfl_sync(0xffffffffu, se.x, j);
            const int   ej   = __shfl_sync(0xffffffffu, se.y, j);
            const float ex   = __shfl_sync(0xffffffffu, exl, j);
            const float4 vv = ((const float4*)(v + (size_t)srcj * 128))[lane];
            acc.x = fmaf(ex, vv.x, acc.x);
            acc.y = fmaf(ex, vv.y, acc.y);
            acc.z = fmaf(ex, vv.z, acc.z);
            acc.w = fmaf(ex, vv.w, acc.w);
            const float2 ev = ((const float2*)(ea + (size_t)ej * 64))[lane];
            sacc.x = fmaf(ex, ev.x, sacc.x);
            sacc.y = fmaf(ex, ev.y, sacc.y);
            den += ex;
        }
    }

    ((float4*)(aggV + (size_t)node * 128))[lane] = acc;
    ((float2*)(sagg + (size_t)node * 64))[lane]  = sacc;
    if (lane == 0) denom[node] = den;
}

// ---------------------------------------------------------------------------
// Final fused: h = (aggV + s @ We)/denom + skip ; LayerNorm ; relu ; gated res.
// ---------------------------------------------------------------------------
__global__ void final_kernel(const float* __restrict__ aggV, const float* __restrict__ sagg,
                             const float* __restrict__ We, const float* __restrict__ skip,
                             const float* __restrict__ denom,
                             const float* __restrict__ res, const float* __restrict__ gate,
                             const float* __restrict__ ln_g, const float* __restrict__ ln_b,
                             float* __restrict__ out, int n) {
    __shared__ float sWe[64 * 128];
    __shared__ float ssm[2][64];
    __shared__ float red[2][4];
    const int tid = threadIdx.x;      // 256
    for (int i = tid; i < 64 * 128; i += 256) sWe[i] = We[i];
    const int grp  = tid >> 7;
    const int c    = tid & 127;
    const int wig  = (tid & 127) >> 5;
    const int lane = tid & 31;
    const float lg = ln_g[c], lb = ln_b[c];
    __syncthreads();

    for (int base = blockIdx.x * 2; base < n; base += gridDim.x * 2) {
        const bool valid = (base + grp) < n;
        const int nn = valid ? (base + grp) : (n - 1);
        __syncthreads();
        if (c < 64) ssm[grp][c] = sagg[(size_t)nn * 64 + c];
        __syncthreads();

        float hraw = aggV[(size_t)nn * 128 + c];
#pragma unroll 4
        for (int d = 0; d < 64; d++) hraw = fmaf(ssm[grp][d], sWe[d * 128 + c], hraw);
        const float dn = denom[nn];
        const float inv = (dn > 0.f) ? (1.f / dn) : 0.f;
        float h = hraw * inv + skip[(size_t)nn * 128 + c];

        float t = h;
#pragma unroll
        for (int o = 16; o > 0; o >>= 1) t += __shfl_xor_sync(0xffffffffu, t, o);
        if (lane == 0) red[grp][wig] = t;
        __syncthreads();
        const float mu = (red[grp][0] + red[grp][1] + red[grp][2] + red[grp][3]) * (1.f / 128.f);
        __syncthreads();

        const float dv = h - mu;
        t = dv * dv;
#pragma unroll
        for (int o = 16; o > 0; o >>= 1) t += __shfl_xor_sync(0xffffffffu, t, o);
        if (lane == 0) red[grp][wig] = t;
        __syncthreads();
        const float var = (red[grp][0] + red[grp][1] + red[grp][2] + red[grp][3]) * (1.f / 128.f);

        float y = dv * rsqrtf(var + 1e-5f) * lg + lb;
        y = fmaxf(y, 0.f);
        const float g = gate[nn];
        const float ov = g * y + (1.f - g) * res[(size_t)nn * 128 + c];
        if (valid) out[(size_t)(base + grp) * 128 + c] = ov;
    }
}

// ---------------------------------------------------------------------------
extern "C" void kernel_launch(void* const* d_in, const int* in_sizes, int n_in,
                              void* d_out, int out_size) {
    const float* x     = (const float*)d_in[0];
    const int*   ei    = (const int*)  d_in[1];
    const float* ea    = (const float*)d_in[2];
    const float* Wq    = (const float*)d_in[3];
    const float* bq    = (const float*)d_in[4];
    const float* Wk    = (const float*)d_in[5];
    const float* bk    = (const float*)d_in[6];
    const float* Wv    = (const float*)d_in[7];
    const float* bv    = (const float*)d_in[8];
    const float* We    = (const float*)d_in[9];
    const float* Wskip = (const float*)d_in[10];
    const float* bskip = (const float*)d_in[11];
    const float* ln_g  = (const float*)d_in[12];
    const float* ln_b  = (const float*)d_in[13];
    const float* Wres  = (const float*)d_in[14];
    const float* bres  = (const float*)d_in[15];
    const float* Wgate = (const float*)d_in[16];
    const float* bgate = (const float*)d_in[17];
    float* out = (float*)d_out;

    int n = in_sizes[0] / 128;
    int ecnt = in_sizes[1] / 2;
    if (n > N_MAX) n = N_MAX;
    if (ecnt > E_MAX) ecnt = E_MAX;

    float *q, *k, *v, *skip, *res, *qe, *sagg, *aggV, *gate, *denom, *exs;
    int *cnt, *rowptr, *wptr, *dsts;
    int2 *srt;
    cudaGetSymbolAddress((void**)&q,      g_q);
    cudaGetSymbolAddress((void**)&k,      g_k);
    cudaGetSymbolAddress((void**)&v,      g_v);
    cudaGetSymbolAddress((void**)&skip,   g_skip);
    cudaGetSymbolAddress((void**)&res,    g_res);
    cudaGetSymbolAddress((void**)&qe,     g_qe);
    cudaGetSymbolAddress((void**)&sagg,   g_s);
    cudaGetSymbolAddress((void**)&aggV,   g_aggV);
    cudaGetSymbolAddress((void**)&gate,   g_gate);
    cudaGetSymbolAddress((void**)&denom,  g_denom);
    cudaGetSymbolAddress((void**)&cnt,    g_cnt);
    cudaGetSymbolAddress((void**)&rowptr, g_rowptr);
    cudaGetSymbolAddress((void**)&wptr,   g_wptr);
    cudaGetSymbolAddress((void**)&srt,    g_srt);
    cudaGetSymbolAddress((void**)&dsts,   g_dsts);
    cudaGetSymbolAddress((void**)&exs,    g_exs);

    const int mma_smem = (64 * SA_STRIDE + 32 * SB_STRIDE) * (int)sizeof(float2);
    cudaFuncSetAttribute(mma_linear5_kernel, cudaFuncAttributeMaxDynamicSharedMemorySize, mma_smem);

    // CSR build (independent of projections)
    zero_cnt_kernel<<<(n + 255) / 256, 256>>>(cnt, n);
    hist_kernel<<<(ecnt + 255) / 256, 256>>>(ei + ecnt, cnt, ecnt);
    scan_kernel<<<1, SCAN_T>>>(cnt, rowptr, wptr, n);
    scatter_kernel<<<(ecnt + 255) / 256, 256>>>(ei, wptr, srt, dsts, ecnt);

    // Node projections (all 5 in one launch; gridDim.y selects weight set)
    dim3 mma_grid((n + 63) / 64, 5, 1);
    mma_linear5_kernel<<<mma_grid, 256, mma_smem>>>(
        x, Wq, bq, q, Wk, bk, k, Wv, bv, v, Wskip, bskip, skip, Wres, bres, res, n);

    qe_kernel<<<740, 128>>>(q, We, qe, n);
    gate_kernel<<<(n + 7) / 8, 256>>>(x, Wgate, bgate, gate, n);

    // Edge-parallel score pass over sorted positions (atomic-free)
    score_kernel<<<(ecnt + 7) / 8, 256>>>(srt, dsts, ea, q, k, qe, exs, ecnt);

    // CSR aggregation, warp per node, broadcast style
    agg2_kernel<<<(n + 7) / 8, 256>>>(rowptr, srt, exs, ea, v, aggV, sagg, denom, n);

    // Final fused epilogue
    final_kernel<<<740, 256>>>(aggV, sagg, We, skip, denom, res, gate, ln_g, ln_b, out, n);
}

// round 7
// speedup vs baseline: 1.3119x; 1.3119x over previous
#include <cuda_runtime.h>
#include <cuda_fp16.h>
#include <math.h>

// Problem constants (fixed by the dataset).
#define N_MAX 50000
#define E_MAX 800000

// -------- scratch (static device globals; no runtime allocation) --------
__device__ __half   g_qh[N_MAX * 128];
__device__ __half   g_kh[N_MAX * 128];
__device__ __half   g_vh[N_MAX * 128];
__device__ __half   g_qeh[N_MAX * 64];
__device__ float    g_skip[N_MAX * 128];
__device__ float    g_res[N_MAX * 128];
__device__ float    g_s[N_MAX * 64];     // sagg (unnormalized)
__device__ float    g_aggV[N_MAX * 128]; // unnormalized Σ ex*v
__device__ float    g_gate[N_MAX];
__device__ float    g_denom[N_MAX];

// ---------------------------------------------------------------------------
// tf32 split: x = hi + lo, both tf32-formatted (usable directly by mma).
// ---------------------------------------------------------------------------
__device__ __forceinline__ float2 tf32_split(float xf) {
    unsigned hi;
    asm("cvt.rna.tf32.f32 %0, %1;" : "=r"(hi) : "f"(xf));
    float lo = xf - __uint_as_float(hi);
    unsigned lob;
    asm("cvt.rna.tf32.f32 %0, %1;" : "=r"(lob) : "f"(lo));
    return make_float2(__uint_as_float(hi), __uint_as_float(lob));
}

__device__ __forceinline__ void mma_tf32(float c[4], const unsigned a[4], const unsigned b[2]) {
    asm volatile(
        "mma.sync.aligned.m16n8k8.row.col.f32.tf32.tf32.f32 "
        "{%0,%1,%2,%3}, {%4,%5,%6,%7}, {%8,%9}, {%0,%1,%2,%3};"
        : "+f"(c[0]), "+f"(c[1]), "+f"(c[2]), "+f"(c[3])
        : "r"(a[0]), "r"(a[1]), "r"(a[2]), "r"(a[3]), "r"(b[0]), "r"(b[1]));
}

// ---------------------------------------------------------------------------
// Node linear via tf32x3 tensor-core MMA (5 weight sets via gridDim.y).
// y = 0,1,2 (q,k,v) write __half output; y = 3,4 (skip,res) write fp32.
// ---------------------------------------------------------------------------
#define SA_STRIDE 36
#define SB_STRIDE 130
__global__ __launch_bounds__(256) void mma_linear5_kernel(
    const float* __restrict__ x,
    const float* __restrict__ Wq, const float* __restrict__ bq, __half* __restrict__ oq,
    const float* __restrict__ Wk, const float* __restrict__ bk, __half* __restrict__ ok,
    const float* __restrict__ Wv, const float* __restrict__ bv, __half* __restrict__ ov,
    const float* __restrict__ Ws, const float* __restrict__ bs, float* __restrict__ os,
    const float* __restrict__ Wr, const float* __restrict__ br, float* __restrict__ orr,
    int n) {
    extern __shared__ float2 dyn[];
    float2* sA = dyn;                     // 64*36
    float2* sB = dyn + 64 * SA_STRIDE;    // 32*130

    const float* W; const float* b;
    __half* outh = 0; float* outf = 0;
    switch (blockIdx.y) {
        case 0: W = Wq; b = bq; outh = oq; break;
        case 1: W = Wk; b = bk; outh = ok; break;
        case 2: W = Wv; b = bv; outh = ov; break;
        case 3: W = Ws; b = bs; outf = os; break;
        default: W = Wr; b = br; outf = orr; break;
    }
    const bool half_out = (blockIdx.y < 3);

    const int tid = threadIdx.x;
    const int wid = tid >> 5, lane = tid & 31;
    const int g = lane >> 2, t4 = lane & 3;
    const int wm = (wid & 1) * 32;
    const int wn = (wid >> 1) * 32;
    const int base = blockIdx.x * 64;

    float acc[2][4][4];
#pragma unroll
    for (int mi = 0; mi < 2; mi++)
#pragma unroll
        for (int ni = 0; ni < 4; ni++)
#pragma unroll
            for (int r = 0; r < 4; r++) acc[mi][ni][r] = 0.f;

    for (int kc = 0; kc < 4; kc++) {
#pragma unroll
        for (int t = 0; t < 2; t++) {
            int i = tid + t * 256;
            int row = i >> 3;
            int c4 = i & 7;
            int gr = base + row; if (gr >= n) gr = n - 1;
            const float4 xv = *(const float4*)(x + (size_t)gr * 128 + kc * 32 + c4 * 4);
            float2* dp = sA + row * SA_STRIDE + c4 * 4;
            dp[0] = tf32_split(xv.x);
            dp[1] = tf32_split(xv.y);
            dp[2] = tf32_split(xv.z);
            dp[3] = tf32_split(xv.w);
        }
#pragma unroll
        for (int t = 0; t < 4; t++) {
            int i = tid + t * 256;
            int row = i >> 5;
            int c4 = i & 31;
            const float4 wv = *(const float4*)(W + (size_t)(kc * 32 + row) * 128 + c4 * 4);
            float2* dp = sB + row * SB_STRIDE + c4 * 4;
            dp[0] = tf32_split(wv.x);
            dp[1] = tf32_split(wv.y);
            dp[2] = tf32_split(wv.z);
            dp[3] = tf32_split(wv.w);
        }
        __syncthreads();

#pragma unroll
        for (int k8 = 0; k8 < 4; k8++) {
            const int kk = k8 * 8;
            unsigned Ahi[2][4], Alo[2][4];
#pragma unroll
            for (int mi = 0; mi < 2; mi++) {
                const int r0 = wm + mi * 16 + g;
                const float2 a00 = sA[r0 * SA_STRIDE + kk + t4];
                const float2 a10 = sA[(r0 + 8) * SA_STRIDE + kk + t4];
                const float2 a01 = sA[r0 * SA_STRIDE + kk + t4 + 4];
                const float2 a11 = sA[(r0 + 8) * SA_STRIDE + kk + t4 + 4];
                Ahi[mi][0] = __float_as_uint(a00.x); Alo[mi][0] = __float_as_uint(a00.y);
                Ahi[mi][1] = __float_as_uint(a10.x); Alo[mi][1] = __float_as_uint(a10.y);
                Ahi[mi][2] = __float_as_uint(a01.x); Alo[mi][2] = __float_as_uint(a01.y);
                Ahi[mi][3] = __float_as_uint(a11.x); Alo[mi][3] = __float_as_uint(a11.y);
            }
            unsigned Bhi[4][2], Blo[4][2];
#pragma unroll
            for (int ni = 0; ni < 4; ni++) {
                const int col = wn + ni * 8 + g;
                const float2 b0 = sB[(kk + t4) * SB_STRIDE + col];
                const float2 b1 = sB[(kk + t4 + 4) * SB_STRIDE + col];
                Bhi[ni][0] = __float_as_uint(b0.x); Blo[ni][0] = __float_as_uint(b0.y);
                Bhi[ni][1] = __float_as_uint(b1.x); Blo[ni][1] = __float_as_uint(b1.y);
            }
#pragma unroll
            for (int mi = 0; mi < 2; mi++)
#pragma unroll
                for (int ni = 0; ni < 4; ni++) {
                    mma_tf32(acc[mi][ni], Ahi[mi], Bhi[ni]);
                    mma_tf32(acc[mi][ni], Ahi[mi], Blo[ni]);
                    mma_tf32(acc[mi][ni], Alo[mi], Bhi[ni]);
                }
        }
        __syncthreads();
    }

#pragma unroll
    for (int ni = 0; ni < 4; ni++) {
        const int col = wn + ni * 8 + 2 * t4;
        const float2 bb = *(const float2*)(b + col);
#pragma unroll
        for (int mi = 0; mi < 2; mi++) {
            const int node0 = base + wm + mi * 16 + g;
            if (node0 < n) {
                float2 o0 = make_float2(acc[mi][ni][0] + bb.x, acc[mi][ni][1] + bb.y);
                if (half_out)
                    *(__half2*)(outh + (size_t)node0 * 128 + col) = __float22half2_rn(o0);
                else
                    *(float2*)(outf + (size_t)node0 * 128 + col) = o0;
            }
            const int node1 = node0 + 8;
            if (node1 < n) {
                float2 o1 = make_float2(acc[mi][ni][2] + bb.x, acc[mi][ni][3] + bb.y);
                if (half_out)
                    *(__half2*)(outh + (size_t)node1 * 128 + col) = __float22half2_rn(o1);
                else
                    *(float2*)(outf + (size_t)node1 * 128 + col) = o1;
            }
        }
    }
}

// ---------------------------------------------------------------------------
// qe[n][d] = sum_c q[n][c] * We[d][c]   (128 -> 64); q input half, qe out half.
// ---------------------------------------------------------------------------
__global__ void qe_kernel(const __half* __restrict__ qh, const float* __restrict__ We,
                          __half* __restrict__ qeh, int n) {
    __shared__ float sWeT[128 * 64];
    __shared__ float sq[16 * 128];
    const int tid = threadIdx.x;       // 128
    for (int i = tid; i < 64 * 128; i += 128) {
        int d = i >> 7, c = i & 127;
        sWeT[c * 64 + d] = We[i];
    }
    __syncthreads();
    const int cg = tid & 15;
    const int ng = tid >> 4;

    for (int base = blockIdx.x * 16; base < n; base += gridDim.x * 16) {
        const int cnt = min(16, n - base);
        __syncthreads();
        for (int i = tid; i < cnt * 64; i += 128) {
            const __half2 hv = ((const __half2*)(qh + (size_t)base * 128))[i];
            const float2 f = __half22float2(hv);
            sq[i * 2] = f.x;
            sq[i * 2 + 1] = f.y;
        }
        __syncthreads();

        float acc[2][4] = {{0.f, 0.f, 0.f, 0.f}, {0.f, 0.f, 0.f, 0.f}};
#pragma unroll 2
        for (int c = 0; c < 128; c++) {
            const float4 w = *((const float4*)(sWeT + c * 64) + cg);
#pragma unroll
            for (int j = 0; j < 2; j++) {
                float xv = sq[(ng * 2 + j) * 128 + c];
                acc[j][0] = fmaf(xv, w.x, acc[j][0]);
                acc[j][1] = fmaf(xv, w.y, acc[j][1]);
                acc[j][2] = fmaf(xv, w.z, acc[j][2]);
                acc[j][3] = fmaf(xv, w.w, acc[j][3]);
            }
        }
#pragma unroll
        for (int j = 0; j < 2; j++) {
            const int node = ng * 2 + j;
            if (node < cnt) {
                const __half2 h0 = __floats2half2_rn(acc[j][0], acc[j][1]);
                const __half2 h1 = __floats2half2_rn(acc[j][2], acc[j][3]);
                uint2 pk;
                pk.x = *(const unsigned*)&h0;
                pk.y = *(const unsigned*)&h1;
                ((uint2*)(qeh + (size_t)(base + node) * 64))[cg] = pk;
            }
        }
    }
}

// ---------------------------------------------------------------------------
// gate[n] = sigmoid(x[n] . Wg + bg)
// ---------------------------------------------------------------------------
__global__ void gate_kernel(const float* __restrict__ x, const float* __restrict__ Wg,
                            const float* __restrict__ bg, float* __restrict__ gate, int n) {
    const int node = blockIdx.x * (blockDim.x >> 5) + (threadIdx.x >> 5);
    const int lane = threadIdx.x & 31;
    if (node >= n) return;
    const float4 a = ((const float4*)(x + (size_t)node * 128))[lane];
    const float4 w = ((const float4*)Wg)[lane];
    float s = a.x * w.x + a.y * w.y + a.z * w.z + a.w * w.w;
#pragma unroll
    for (int o = 16; o > 0; o >>= 1) s += __shfl_xor_sync(0xffffffffu, s, o);
    if (lane == 0) gate[node] = 1.f / (1.f + __expf(-(s + bg[0])));
}

// ---------------------------------------------------------------------------
// init: fast grid-stride float4 zeroing of accumulators.
// ---------------------------------------------------------------------------
__global__ void init_kernel(float4* __restrict__ aggV4, float4* __restrict__ sagg4,
                            float* __restrict__ denom, int n) {
    const float4 z = make_float4(0.f, 0.f, 0.f, 0.f);
    const int stride = gridDim.x * blockDim.x;
    const int t = blockIdx.x * blockDim.x + threadIdx.x;
    for (int i = t; i < n * 32; i += stride) aggV4[i] = z;
    for (int i = t; i < n * 16; i += stride) sagg4[i] = z;
    for (int i = t; i < n; i += stride) denom[i] = 0.f;
}

// ---------------------------------------------------------------------------
// Fused single edge pass (max-free softmax, unnormalized aggregation):
//   ex = exp((q[dst].k[src] + qe[dst].ea_e)/sqrt(128))
//   denom[dst] += ex ; aggV[dst] += ex*v[src] ; sagg[dst] += ex*ea_e
// One warp per edge; q/k/v/qe are fp16 (half gather traffic).
// ---------------------------------------------------------------------------
__device__ __forceinline__ void red_add_v4(float* p, float a, float b, float c, float d) {
    asm volatile("red.global.add.v4.f32 [%0], {%1, %2, %3, %4};"
                 :: "l"(p), "f"(a), "f"(b), "f"(c), "f"(d) : "memory");
}
__device__ __forceinline__ void red_add_v2(float* p, float a, float b) {
    asm volatile("red.global.add.v2.f32 [%0], {%1, %2};"
                 :: "l"(p), "f"(a), "f"(b) : "memory");
}

__global__ __launch_bounds__(256) void edge_fused_kernel(
    const int* __restrict__ ei, const float* __restrict__ ea,
    const __half* __restrict__ qh, const __half* __restrict__ kh,
    const __half* __restrict__ qeh, const __half* __restrict__ vh,
    float* __restrict__ denom, float* __restrict__ aggV,
    float* __restrict__ sagg, int ecnt) {
    const int e = blockIdx.x * (blockDim.x >> 5) + (threadIdx.x >> 5);
    const int lane = threadIdx.x & 31;
    if (e >= ecnt) return;
    const int src = ei[e];
    const int dst = ei[ecnt + e];

    // q[dst], k[src]: 4 halves per lane (uint2 = 8B), 32 lanes cover 128 dims
    const uint2 qb = ((const uint2*)(qh + (size_t)dst * 128))[lane];
    const uint2 kb = ((const uint2*)(kh + (size_t)src * 128))[lane];
    const float2 q0 = __half22float2(*(const __half2*)&qb.x);
    const float2 q1 = __half22float2(*(const __half2*)&qb.y);
    const float2 k0 = __half22float2(*(const __half2*)&kb.x);
    const float2 k1 = __half22float2(*(const __half2*)&kb.y);
    float s = q0.x * k0.x + q0.y * k0.y + q1.x * k1.x + q1.y * k1.y;

    // qe[dst]: 2 halves per lane; ea: 2 floats per lane (64 dims)
    const unsigned qeb = ((const unsigned*)(qeh + (size_t)dst * 64))[lane];
    const float2 qe2 = __half22float2(*(const __half2*)&qeb);
    const float2 ev = ((const float2*)(ea + (size_t)e * 64))[lane];
    s += qe2.x * ev.x + qe2.y * ev.y;

#pragma unroll
    for (int o = 16; o > 0; o >>= 1) s += __shfl_xor_sync(0xffffffffu, s, o);
    const float ex = __expf(s * 0.08838834764831845f);   // 1/sqrt(128)
    if (lane == 0) atomicAdd(&denom[dst], ex);

    // v[src]: 4 halves per lane
    const uint2 vb = ((const uint2*)(vh + (size_t)src * 128))[lane];
    const float2 v0 = __half22float2(*(const __half2*)&vb.x);
    const float2 v1 = __half22float2(*(const __half2*)&vb.y);
    red_add_v4(aggV + (size_t)dst * 128 + lane * 4,
               ex * v0.x, ex * v0.y, ex * v1.x, ex * v1.y);
    red_add_v2(sagg + (size_t)dst * 64 + lane * 2, ex * ev.x, ex * ev.y);
}

// ---------------------------------------------------------------------------
// Final fused: h = (aggV + s @ We)/denom + skip ; LayerNorm ; relu ; gated res.
// ---------------------------------------------------------------------------
__global__ void final_kernel(const float* __restrict__ aggV, const float* __restrict__ sagg,
                             const float* __restrict__ We, const float* __restrict__ skip,
                             const float* __restrict__ denom,
                             const float* __restrict__ res, const float* __restrict__ gate,
                             const float* __restrict__ ln_g, const float* __restrict__ ln_b,
                             float* __restrict__ out, int n) {
    __shared__ float sWe[64 * 128];
    __shared__ float ssm[2][64];
    __shared__ float red[2][4];
    const int tid = threadIdx.x;      // 256
    for (int i = tid; i < 64 * 128; i += 256) sWe[i] = We[i];
    const int grp  = tid >> 7;
    const int c    = tid & 127;
    const int wig  = (tid & 127) >> 5;
    const int lane = tid & 31;
    const float lg = ln_g[c], lb = ln_b[c];
    __syncthreads();

    for (int base = blockIdx.x * 2; base < n; base += gridDim.x * 2) {
        const bool valid = (base + grp) < n;
        const int nn = valid ? (base + grp) : (n - 1);
        __syncthreads();
        if (c < 64) ssm[grp][c] = sagg[(size_t)nn * 64 + c];
        __syncthreads();

        float hraw = aggV[(size_t)nn * 128 + c];
#pragma unroll 4
        for (int d = 0; d < 64; d++) hraw = fmaf(ssm[grp][d], sWe[d * 128 + c], hraw);
        const float dn = denom[nn];
        const float inv = (dn > 0.f) ? (1.f / dn) : 0.f;
        float h = hraw * inv + skip[(size_t)nn * 128 + c];

        float t = h;
#pragma unroll
        for (int o = 16; o > 0; o >>= 1) t += __shfl_xor_sync(0xffffffffu, t, o);
        if (lane == 0) red[grp][wig] = t;
        __syncthreads();
        const float mu = (red[grp][0] + red[grp][1] + red[grp][2] + red[grp][3]) * (1.f / 128.f);
        __syncthreads();

        const float dv = h - mu;
        t = dv * dv;
#pragma unroll
        for (int o = 16; o > 0; o >>= 1) t += __shfl_xor_sync(0xffffffffu, t, o);
        if (lane == 0) red[grp][wig] = t;
        __syncthreads();
        const float var = (red[grp][0] + red[grp][1] + red[grp][2] + red[grp][3]) * (1.f / 128.f);

        float y = dv * rsqrtf(var + 1e-5f) * lg + lb;
        y = fmaxf(y, 0.f);
        const float g = gate[nn];
        const float ov = g * y + (1.f - g) * res[(size_t)nn * 128 + c];
        if (valid) out[(size_t)(base + grp) * 128 + c] = ov;
    }
}

// ---------------------------------------------------------------------------
extern "C" void kernel_launch(void* const* d_in, const int* in_sizes, int n_in,
                              void* d_out, int out_size) {
    const float* x     = (const float*)d_in[0];
    const int*   ei    = (const int*)  d_in[1];
    const float* ea    = (const float*)d_in[2];
    const float* Wq    = (const float*)d_in[3];
    const float* bq    = (const float*)d_in[4];
    const float* Wk    = (const float*)d_in[5];
    const float* bk    = (const float*)d_in[6];
    const float* Wv    = (const float*)d_in[7];
    const float* bv    = (const float*)d_in[8];
    const float* We    = (const float*)d_in[9];
    const float* Wskip = (const float*)d_in[10];
    const float* bskip = (const float*)d_in[11];
    const float* ln_g  = (const float*)d_in[12];
    const float* ln_b  = (const float*)d_in[13];
    const float* Wres  = (const float*)d_in[14];
    const float* bres  = (const float*)d_in[15];
    const float* Wgate = (const float*)d_in[16];
    const float* bgate = (const float*)d_in[17];
    float* out = (float*)d_out;

    int n = in_sizes[0] / 128;
    int ecnt = in_sizes[1] / 2;
    if (n > N_MAX) n = N_MAX;
    if (ecnt > E_MAX) ecnt = E_MAX;

    __half *qhp, *khp, *vhp, *qehp;
    float *skip, *res, *sagg, *aggV, *gate, *denom;
    cudaGetSymbolAddress((void**)&qhp,   g_qh);
    cudaGetSymbolAddress((void**)&khp,   g_kh);
    cudaGetSymbolAddress((void**)&vhp,   g_vh);
    cudaGetSymbolAddress((void**)&qehp,  g_qeh);
    cudaGetSymbolAddress((void**)&skip,  g_skip);
    cudaGetSymbolAddress((void**)&res,   g_res);
    cudaGetSymbolAddress((void**)&sagg,  g_s);
    cudaGetSymbolAddress((void**)&aggV,  g_aggV);
    cudaGetSymbolAddress((void**)&gate,  g_gate);
    cudaGetSymbolAddress((void**)&denom, g_denom);

    const int mma_smem = (64 * SA_STRIDE + 32 * SB_STRIDE) * (int)sizeof(float2);
    cudaFuncSetAttribute(mma_linear5_kernel, cudaFuncAttributeMaxDynamicSharedMemorySize, mma_smem);

    // All 5 node projections in one launch (q/k/v -> fp16, skip/res -> fp32)
    dim3 mma_grid((n + 63) / 64, 5, 1);
    mma_linear5_kernel<<<mma_grid, 256, mma_smem>>>(
        x, Wq, bq, qhp, Wk, bk, khp, Wv, bv, vhp, Wskip, bskip, skip, Wres, bres, res, n);

    qe_kernel<<<740, 128>>>(qhp, We, qehp, n);
    gate_kernel<<<(n + 7) / 8, 256>>>(x, Wgate, bgate, gate, n);

    // init accumulators (grid-stride vectorized)
    init_kernel<<<592, 256>>>((float4*)aggV, (float4*)sagg, denom, n);

    // Single fused edge pass (fp16 gathers)
    edge_fused_kernel<<<(ecnt + 7) / 8, 256>>>(ei, ea, qhp, khp, qehp, vhp,
                                               denom, aggV, sagg, ecnt);

    // Final fused epilogue
    final_kernel<<<740, 256>>>(aggV, sagg, We, skip, denom, res, gate, ln_g, ln_b, out, n);
}

// round 9
// speedup vs baseline: 1.3541x; 1.0321x over previous
#include <cuda_runtime.h>
#include <cuda_fp16.h>
#include <math.h>

// Problem constants (fixed by the dataset).
#define N_MAX 50000
#define E_MAX 800000

// -------- scratch (static device globals; no runtime allocation) --------
__device__ __half   g_qh[N_MAX * 128];
__device__ __half   g_kh[N_MAX * 128];
__device__ __half   g_vh[N_MAX * 128];
__device__ __half   g_qeh[N_MAX * 64];
__device__ float    g_skip[N_MAX * 128];
__device__ float    g_res[N_MAX * 128];
__device__ float    g_s[N_MAX * 64];     // sagg (unnormalized)
__device__ float    g_aggV[N_MAX * 128]; // unnormalized Σ ex*v
__device__ float    g_gate[N_MAX];
__device__ float    g_denom[N_MAX];

// ---------------------------------------------------------------------------
// tf32 split: x = hi + lo, both tf32-formatted (usable directly by mma).
// ---------------------------------------------------------------------------
__device__ __forceinline__ float2 tf32_split(float xf) {
    unsigned hi;
    asm("cvt.rna.tf32.f32 %0, %1;" : "=r"(hi) : "f"(xf));
    float lo = xf - __uint_as_float(hi);
    unsigned lob;
    asm("cvt.rna.tf32.f32 %0, %1;" : "=r"(lob) : "f"(lo));
    return make_float2(__uint_as_float(hi), __uint_as_float(lob));
}

__device__ __forceinline__ void mma_tf32(float c[4], const unsigned a[4], const unsigned b[2]) {
    asm volatile(
        "mma.sync.aligned.m16n8k8.row.col.f32.tf32.tf32.f32 "
        "{%0,%1,%2,%3}, {%4,%5,%6,%7}, {%8,%9}, {%0,%1,%2,%3};"
        : "+f"(c[0]), "+f"(c[1]), "+f"(c[2]), "+f"(c[3])
        : "r"(a[0]), "r"(a[1]), "r"(a[2]), "r"(a[3]), "r"(b[0]), "r"(b[1]));
}

// ---------------------------------------------------------------------------
// Node linear via tf32x3 tensor-core MMA (5 weight sets via gridDim.y).
// y = 0,1,2 (q,k,v) write __half output; y = 3,4 (skip,res) write fp32.
// ---------------------------------------------------------------------------
#define SA_STRIDE 36
#define SB_STRIDE 130
__global__ __launch_bounds__(256) void mma_linear5_kernel(
    const float* __restrict__ x,
    const float* __restrict__ Wq, const float* __restrict__ bq, __half* __restrict__ oq,
    const float* __restrict__ Wk, const float* __restrict__ bk, __half* __restrict__ ok,
    const float* __restrict__ Wv, const float* __restrict__ bv, __half* __restrict__ ov,
    const float* __restrict__ Ws, const float* __restrict__ bs, float* __restrict__ os,
    const float* __restrict__ Wr, const float* __restrict__ br, float* __restrict__ orr,
    int n) {
    extern __shared__ float2 dyn[];
    float2* sA = dyn;                     // 64*36
    float2* sB = dyn + 64 * SA_STRIDE;    // 32*130

    const float* W; const float* b;
    __half* outh = 0; float* outf = 0;
    switch (blockIdx.y) {
        case 0: W = Wq; b = bq; outh = oq; break;
        case 1: W = Wk; b = bk; outh = ok; break;
        case 2: W = Wv; b = bv; outh = ov; break;
        case 3: W = Ws; b = bs; outf = os; break;
        default: W = Wr; b = br; outf = orr; break;
    }
    const bool half_out = (blockIdx.y < 3);

    const int tid = threadIdx.x;
    const int wid = tid >> 5, lane = tid & 31;
    const int g = lane >> 2, t4 = lane & 3;
    const int wm = (wid & 1) * 32;
    const int wn = (wid >> 1) * 32;
    const int base = blockIdx.x * 64;

    float acc[2][4][4];
#pragma unroll
    for (int mi = 0; mi < 2; mi++)
#pragma unroll
        for (int ni = 0; ni < 4; ni++)
#pragma unroll
            for (int r = 0; r < 4; r++) acc[mi][ni][r] = 0.f;

    for (int kc = 0; kc < 4; kc++) {
#pragma unroll
        for (int t = 0; t < 2; t++) {
            int i = tid + t * 256;
            int row = i >> 3;
            int c4 = i & 7;
            int gr = base + row; if (gr >= n) gr = n - 1;
            const float4 xv = *(const float4*)(x + (size_t)gr * 128 + kc * 32 + c4 * 4);
            float2* dp = sA + row * SA_STRIDE + c4 * 4;
            dp[0] = tf32_split(xv.x);
            dp[1] = tf32_split(xv.y);
            dp[2] = tf32_split(xv.z);
            dp[3] = tf32_split(xv.w);
        }
#pragma unroll
        for (int t = 0; t < 4; t++) {
            int i = tid + t * 256;
            int row = i >> 5;
            int c4 = i & 31;
            const float4 wv = *(const float4*)(W + (size_t)(kc * 32 + row) * 128 + c4 * 4);
            float2* dp = sB + row * SB_STRIDE + c4 * 4;
            dp[0] = tf32_split(wv.x);
            dp[1] = tf32_split(wv.y);
            dp[2] = tf32_split(wv.z);
            dp[3] = tf32_split(wv.w);
        }
        __syncthreads();

#pragma unroll
        for (int k8 = 0; k8 < 4; k8++) {
            const int kk = k8 * 8;
            unsigned Ahi[2][4], Alo[2][4];
#pragma unroll
            for (int mi = 0; mi < 2; mi++) {
                const int r0 = wm + mi * 16 + g;
                const float2 a00 = sA[r0 * SA_STRIDE + kk + t4];
                const float2 a10 = sA[(r0 + 8) * SA_STRIDE + kk + t4];
                const float2 a01 = sA[r0 * SA_STRIDE + kk + t4 + 4];
                const float2 a11 = sA[(r0 + 8) * SA_STRIDE + kk + t4 + 4];
                Ahi[mi][0] = __float_as_uint(a00.x); Alo[mi][0] = __float_as_uint(a00.y);
                Ahi[mi][1] = __float_as_uint(a10.x); Alo[mi][1] = __float_as_uint(a10.y);
                Ahi[mi][2] = __float_as_uint(a01.x); Alo[mi][2] = __float_as_uint(a01.y);
                Ahi[mi][3] = __float_as_uint(a11.x); Alo[mi][3] = __float_as_uint(a11.y);
            }
            unsigned Bhi[4][2], Blo[4][2];
#pragma unroll
            for (int ni = 0; ni < 4; ni++) {
                const int col = wn + ni * 8 + g;
                const float2 b0 = sB[(kk + t4) * SB_STRIDE + col];
                const float2 b1 = sB[(kk + t4 + 4) * SB_STRIDE + col];
                Bhi[ni][0] = __float_as_uint(b0.x); Blo[ni][0] = __float_as_uint(b0.y);
                Bhi[ni][1] = __float_as_uint(b1.x); Blo[ni][1] = __float_as_uint(b1.y);
            }
#pragma unroll
            for (int mi = 0; mi < 2; mi++)
#pragma unroll
                for (int ni = 0; ni < 4; ni++) {
                    mma_tf32(acc[mi][ni], Ahi[mi], Bhi[ni]);
                    mma_tf32(acc[mi][ni], Ahi[mi], Blo[ni]);
                    mma_tf32(acc[mi][ni], Alo[mi], Bhi[ni]);
                }
        }
        __syncthreads();
    }

#pragma unroll
    for (int ni = 0; ni < 4; ni++) {
        const int col = wn + ni * 8 + 2 * t4;
        const float2 bb = *(const float2*)(b + col);
#pragma unroll
        for (int mi = 0; mi < 2; mi++) {
            const int node0 = base + wm + mi * 16 + g;
            if (node0 < n) {
                float2 o0 = make_float2(acc[mi][ni][0] + bb.x, acc[mi][ni][1] + bb.y);
                if (half_out)
                    *(__half2*)(outh + (size_t)node0 * 128 + col) = __float22half2_rn(o0);
                else
                    *(float2*)(outf + (size_t)node0 * 128 + col) = o0;
            }
            const int node1 = node0 + 8;
            if (node1 < n) {
                float2 o1 = make_float2(acc[mi][ni][2] + bb.x, acc[mi][ni][3] + bb.y);
                if (half_out)
                    *(__half2*)(outh + (size_t)node1 * 128 + col) = __float22half2_rn(o1);
                else
                    *(float2*)(outf + (size_t)node1 * 128 + col) = o1;
            }
        }
    }
}

// ---------------------------------------------------------------------------
// qe[n][d] = sum_c q[n][c] * We[d][c]   (128 -> 64); q input half, qe out half.
// ---------------------------------------------------------------------------
__global__ void qe_kernel(const __half* __restrict__ qh, const float* __restrict__ We,
                          __half* __restrict__ qeh, int n) {
    __shared__ float sWeT[128 * 64];
    __shared__ float sq[16 * 128];
    const int tid = threadIdx.x;       // 128
    for (int i = tid; i < 64 * 128; i += 128) {
        int d = i >> 7, c = i & 127;
        sWeT[c * 64 + d] = We[i];
    }
    __syncthreads();
    const int cg = tid & 15;
    const int ng = tid >> 4;

    for (int base = blockIdx.x * 16; base < n; base += gridDim.x * 16) {
        const int cnt = min(16, n - base);
        __syncthreads();
        for (int i = tid; i < cnt * 64; i += 128) {
            const __half2 hv = ((const __half2*)(qh + (size_t)base * 128))[i];
            const float2 f = __half22float2(hv);
            sq[i * 2] = f.x;
            sq[i * 2 + 1] = f.y;
        }
        __syncthreads();

        float acc[2][4] = {{0.f, 0.f, 0.f, 0.f}, {0.f, 0.f, 0.f, 0.f}};
#pragma unroll 2
        for (int c = 0; c < 128; c++) {
            const float4 w = *((const float4*)(sWeT + c * 64) + cg);
#pragma unroll
            for (int j = 0; j < 2; j++) {
                float xv = sq[(ng * 2 + j) * 128 + c];
                acc[j][0] = fmaf(xv, w.x, acc[j][0]);
                acc[j][1] = fmaf(xv, w.y, acc[j][1]);
                acc[j][2] = fmaf(xv, w.z, acc[j][2]);
                acc[j][3] = fmaf(xv, w.w, acc[j][3]);
            }
        }
#pragma unroll
        for (int j = 0; j < 2; j++) {
            const int node = ng * 2 + j;
            if (node < cnt) {
                const __half2 h0 = __floats2half2_rn(acc[j][0], acc[j][1]);
                const __half2 h1 = __floats2half2_rn(acc[j][2], acc[j][3]);
                uint2 pk;
                pk.x = *(const unsigned*)&h0;
                pk.y = *(const unsigned*)&h1;
                ((uint2*)(qeh + (size_t)(base + node) * 64))[cg] = pk;
            }
        }
    }
}

// ---------------------------------------------------------------------------
// gate[n] = sigmoid(x[n] . Wg + bg)
// ---------------------------------------------------------------------------
__global__ void gate_kernel(const float* __restrict__ x, const float* __restrict__ Wg,
                            const float* __restrict__ bg, float* __restrict__ gate, int n) {
    const int node = blockIdx.x * (blockDim.x >> 5) + (threadIdx.x >> 5);
    const int lane = threadIdx.x & 31;
    if (node >= n) return;
    const float4 a = ((const float4*)(x + (size_t)node * 128))[lane];
    const float4 w = ((const float4*)Wg)[lane];
    float s = a.x * w.x + a.y * w.y + a.z * w.z + a.w * w.w;
#pragma unroll
    for (int o = 16; o > 0; o >>= 1) s += __shfl_xor_sync(0xffffffffu, s, o);
    if (lane == 0) gate[node] = 1.f / (1.f + __expf(-(s + bg[0])));
}

// ---------------------------------------------------------------------------
// init: fast grid-stride float4 zeroing of accumulators.
// ---------------------------------------------------------------------------
__global__ void init_kernel(float4* __restrict__ aggV4, float4* __restrict__ sagg4,
                            float* __restrict__ denom, int n) {
    const float4 z = make_float4(0.f, 0.f, 0.f, 0.f);
    const int stride = gridDim.x * blockDim.x;
    const int t = blockIdx.x * blockDim.x + threadIdx.x;
    for (int i = t; i < n * 32; i += stride) aggV4[i] = z;
    for (int i = t; i < n * 16; i += stride) sagg4[i] = z;
    for (int i = t; i < n; i += stride) denom[i] = 0.f;
}

// ---------------------------------------------------------------------------
// Fused edge pass, ILP-4: each warp handles 4 consecutive edges.
// All gather loads for all 4 edges are issued before any reduction, giving
// ~20 independent LDGs in flight per warp (latency hiding without occupancy).
// ---------------------------------------------------------------------------
__device__ __forceinline__ void red_add_v4(float* p, float a, float b, float c, float d) {
    asm volatile("red.global.add.v4.f32 [%0], {%1, %2, %3, %4};"
                 :: "l"(p), "f"(a), "f"(b), "f"(c), "f"(d) : "memory");
}
__device__ __forceinline__ void red_add_v2(float* p, float a, float b) {
    asm volatile("red.global.add.v2.f32 [%0], {%1, %2};"
                 :: "l"(p), "f"(a), "f"(b) : "memory");
}

__global__ __launch_bounds__(256) void edge_fused_kernel(
    const int* __restrict__ ei, const float* __restrict__ ea,
    const __half* __restrict__ qh, const __half* __restrict__ kh,
    const __half* __restrict__ qeh, const __half* __restrict__ vh,
    float* __restrict__ denom, float* __restrict__ aggV,
    float* __restrict__ sagg, int ecnt) {
    const int warp = blockIdx.x * (blockDim.x >> 5) + (threadIdx.x >> 5);
    const int lane = threadIdx.x & 31;
    const int e0 = warp * 4;
    if (e0 >= ecnt) return;
    const int m = min(4, ecnt - e0);

    // Lane-parallel index fetch: lanes 0-3 load src[e0+j], lanes 4-7 load dst[e0+j].
    int idx = 0;
    if (lane < 4) {
        if (lane < m) idx = ei[e0 + lane];
    } else if (lane < 8) {
        if (lane - 4 < m) idx = ei[ecnt + e0 + lane - 4];
    }
    int srcs[4], dsts[4];
#pragma unroll
    for (int j = 0; j < 4; j++) {
        srcs[j] = __shfl_sync(0xffffffffu, idx, j);
        dsts[j] = __shfl_sync(0xffffffffu, idx, 4 + j);
    }

    // ---- issue ALL gathers up front (q,k,qe,ea,v per edge) ----
    uint2 qb[4], kb[4], vb[4];
    unsigned qeb[4];
    float2 ev[4];
#pragma unroll
    for (int j = 0; j < 4; j++) {
        const int jj = (j < m) ? j : 0;        // clamp: redundant-but-safe loads
        qb[j]  = ((const uint2*)(qh + (size_t)dsts[jj] * 128))[lane];
        kb[j]  = ((const uint2*)(kh + (size_t)srcs[jj] * 128))[lane];
        qeb[j] = ((const unsigned*)(qeh + (size_t)dsts[jj] * 64))[lane];
        ev[j]  = ((const float2*)(ea + (size_t)(e0 + jj) * 64))[lane];
        vb[j]  = ((const uint2*)(vh + (size_t)srcs[jj] * 128))[lane];
    }

    // ---- 4 interleaved dot products ----
    float s[4];
#pragma unroll
    for (int j = 0; j < 4; j++) {
        const float2 q0 = __half22float2(*(const __half2*)&qb[j].x);
        const float2 q1 = __half22float2(*(const __half2*)&qb[j].y);
        const float2 k0 = __half22float2(*(const __half2*)&kb[j].x);
        const float2 k1 = __half22float2(*(const __half2*)&kb[j].y);
        const float2 qe2 = __half22float2(*(const __half2*)&qeb[j]);
        s[j] = q0.x * k0.x + q0.y * k0.y + q1.x * k1.x + q1.y * k1.y
             + qe2.x * ev[j].x + qe2.y * ev[j].y;
    }
    // interleaved butterfly reductions (4 independent chains)
#pragma unroll
    for (int o = 16; o > 0; o >>= 1) {
#pragma unroll
        for (int j = 0; j < 4; j++) s[j] += __shfl_xor_sync(0xffffffffu, s[j], o);
    }
    float ex[4];
#pragma unroll
    for (int j = 0; j < 4; j++) ex[j] = __expf(s[j] * 0.08838834764831845f);

    // ---- reductions ----
#pragma unroll
    for (int j = 0; j < 4; j++) {
        if (j >= m) break;
        const float2 v0 = __half22float2(*(const __half2*)&vb[j].x);
        const float2 v1 = __half22float2(*(const __half2*)&vb[j].y);
        red_add_v4(aggV + (size_t)dsts[j] * 128 + lane * 4,
                   ex[j] * v0.x, ex[j] * v0.y, ex[j] * v1.x, ex[j] * v1.y);
        red_add_v2(sagg + (size_t)dsts[j] * 64 + lane * 2,
                   ex[j] * ev[j].x, ex[j] * ev[j].y);
        if (lane == 0) atomicAdd(&denom[dsts[j]], ex[j]);
    }
}

// ---------------------------------------------------------------------------
// Final fused: h = (aggV + s @ We)/denom + skip ; LayerNorm ; relu ; gated res.
// ---------------------------------------------------------------------------
__global__ void final_kernel(const float* __restrict__ aggV, const float* __restrict__ sagg,
                             const float* __restrict__ We, const float* __restrict__ skip,
                             const float* __restrict__ denom,
                             const float* __restrict__ res, const float* __restrict__ gate,
                             const float* __restrict__ ln_g, const float* __restrict__ ln_b,
                             float* __restrict__ out, int n) {
    __shared__ float sWe[64 * 128];
    __shared__ float ssm[2][64];
    __shared__ float red[2][4];
    const int tid = threadIdx.x;      // 256
    for (int i = tid; i < 64 * 128; i += 256) sWe[i] = We[i];
    const int grp  = tid >> 7;
    const int c    = tid & 127;
    const int wig  = (tid & 127) >> 5;
    const int lane = tid & 31;
    const float lg = ln_g[c], lb = ln_b[c];
    __syncthreads();

    for (int base = blockIdx.x * 2; base < n; base += gridDim.x * 2) {
        const bool valid = (base + grp) < n;
        const int nn = valid ? (base + grp) : (n - 1);
        __syncthreads();
        if (c < 64) ssm[grp][c] = sagg[(size_t)nn * 64 + c];
        __syncthreads();

        float hraw = aggV[(size_t)nn * 128 + c];
#pragma unroll 4
        for (int d = 0; d < 64; d++) hraw = fmaf(ssm[grp][d], sWe[d * 128 + c], hraw);
        const float dn = denom[nn];
        const float inv = (dn > 0.f) ? (1.f / dn) : 0.f;
        float h = hraw * inv + skip[(size_t)nn * 128 + c];

        float t = h;
#pragma unroll
        for (int o = 16; o > 0; o >>= 1) t += __shfl_xor_sync(0xffffffffu, t, o);
        if (lane == 0) red[grp][wig] = t;
        __syncthreads();
        const float mu = (red[grp][0] + red[grp][1] + red[grp][2] + red[grp][3]) * (1.f / 128.f);
        __syncthreads();

        const float dv = h - mu;
        t = dv * dv;
#pragma unroll
        for (int o = 16; o > 0; o >>= 1) t += __shfl_xor_sync(0xffffffffu, t, o);
        if (lane == 0) red[grp][wig] = t;
        __syncthreads();
        const float var = (red[grp][0] + red[grp][1] + red[grp][2] + red[grp][3]) * (1.f / 128.f);

        float y = dv * rsqrtf(var + 1e-5f) * lg + lb;
        y = fmaxf(y, 0.f);
        const float g = gate[nn];
        const float ov = g * y + (1.f - g) * res[(size_t)nn * 128 + c];
        if (valid) out[(size_t)(base + grp) * 128 + c] = ov;
    }
}

// ---------------------------------------------------------------------------
extern "C" void kernel_launch(void* const* d_in, const int* in_sizes, int n_in,
                              void* d_out, int out_size) {
    const float* x     = (const float*)d_in[0];
    const int*   ei    = (const int*)  d_in[1];
    const float* ea    = (const float*)d_in[2];
    const float* Wq    = (const float*)d_in[3];
    const float* bq    = (const float*)d_in[4];
    const float* Wk    = (const float*)d_in[5];
    const float* bk    = (const float*)d_in[6];
    const float* Wv    = (const float*)d_in[7];
    const float* bv    = (const float*)d_in[8];
    const float* We    = (const float*)d_in[9];
    const float* Wskip = (const float*)d_in[10];
    const float* bskip = (const float*)d_in[11];
    const float* ln_g  = (const float*)d_in[12];
    const float* ln_b  = (const float*)d_in[13];
    const float* Wres  = (const float*)d_in[14];
    const float* bres  = (const float*)d_in[15];
    const float* Wgate = (const float*)d_in[16];
    const float* bgate = (const float*)d_in[17];
    float* out = (float*)d_out;

    int n = in_sizes[0] / 128;
    int ecnt = in_sizes[1] / 2;
    if (n > N_MAX) n = N_MAX;
    if (ecnt > E_MAX) ecnt = E_MAX;

    __half *qhp, *khp, *vhp, *qehp;
    float *skip, *res, *sagg, *aggV, *gate, *denom;
    cudaGetSymbolAddress((void**)&qhp,   g_qh);
    cudaGetSymbolAddress((void**)&khp,   g_kh);
    cudaGetSymbolAddress((void**)&vhp,   g_vh);
    cudaGetSymbolAddress((void**)&qehp,  g_qeh);
    cudaGetSymbolAddress((void**)&skip,  g_skip);
    cudaGetSymbolAddress((void**)&res,   g_res);
    cudaGetSymbolAddress((void**)&sagg,  g_s);
    cudaGetSymbolAddress((void**)&aggV,  g_aggV);
    cudaGetSymbolAddress((void**)&gate,  g_gate);
    cudaGetSymbolAddress((void**)&denom, g_denom);

    const int mma_smem = (64 * SA_STRIDE + 32 * SB_STRIDE) * (int)sizeof(float2);
    cudaFuncSetAttribute(mma_linear5_kernel, cudaFuncAttributeMaxDynamicSharedMemorySize, mma_smem);

    // All 5 node projections in one launch (q/k/v -> fp16, skip/res -> fp32)
    dim3 mma_grid((n + 63) / 64, 5, 1);
    mma_linear5_kernel<<<mma_grid, 256, mma_smem>>>(
        x, Wq, bq, qhp, Wk, bk, khp, Wv, bv, vhp, Wskip, bskip, skip, Wres, bres, res, n);

    qe_kernel<<<740, 128>>>(qhp, We, qehp, n);
    gate_kernel<<<(n + 7) / 8, 256>>>(x, Wgate, bgate, gate, n);

    // init accumulators (grid-stride vectorized)
    init_kernel<<<592, 256>>>((float4*)aggV, (float4*)sagg, denom, n);

    // Single fused edge pass, 4 edges per warp (ILP-4)
    const int nwarps = (ecnt + 3) / 4;
    edge_fused_kernel<<<(nwarps + 7) / 8, 256>>>(ei, ea, qhp, khp, qehp, vhp,
                                                 denom, aggV, sagg, ecnt);

    // Final fused epilogue
    final_kernel<<<740, 256>>>(aggV, sagg, We, skip, denom, res, gate, ln_g, ln_b, out, n);
}

// round 10
// speedup vs baseline: 1.4631x; 1.0805x over previous
#include <cuda_runtime.h>
#include <cuda_fp16.h>
#include <math.h>

// Problem constants (fixed by the dataset).
#define N_MAX 50000
#define E_MAX 800000

// -------- scratch (static device globals; no runtime allocation) --------
__device__ __half   g_qh[N_MAX * 128];
__device__ __half   g_kh[N_MAX * 128];
__device__ __half   g_vh[N_MAX * 128];
__device__ __half   g_qeh[N_MAX * 64];
__device__ float    g_skip[N_MAX * 128];
__device__ float    g_res[N_MAX * 128];
__device__ __half   g_sh[N_MAX * 64];     // sagg (fp16, unnormalized)
__device__ __half   g_aggVh[N_MAX * 128]; // fp16, unnormalized Σ ex*v
__device__ float    g_gate[N_MAX];
__device__ float    g_denom[N_MAX];

// ---------------------------------------------------------------------------
// tf32 split: x = hi + lo, both tf32-formatted (usable directly by mma).
// ---------------------------------------------------------------------------
__device__ __forceinline__ float2 tf32_split(float xf) {
    unsigned hi;
    asm("cvt.rna.tf32.f32 %0, %1;" : "=r"(hi) : "f"(xf));
    float lo = xf - __uint_as_float(hi);
    unsigned lob;
    asm("cvt.rna.tf32.f32 %0, %1;" : "=r"(lob) : "f"(lo));
    return make_float2(__uint_as_float(hi), __uint_as_float(lob));
}

__device__ __forceinline__ void mma_tf32(float c[4], const unsigned a[4], const unsigned b[2]) {
    asm volatile(
        "mma.sync.aligned.m16n8k8.row.col.f32.tf32.tf32.f32 "
        "{%0,%1,%2,%3}, {%4,%5,%6,%7}, {%8,%9}, {%0,%1,%2,%3};"
        : "+f"(c[0]), "+f"(c[1]), "+f"(c[2]), "+f"(c[3])
        : "r"(a[0]), "r"(a[1]), "r"(a[2]), "r"(a[3]), "r"(b[0]), "r"(b[1]));
}

// ---------------------------------------------------------------------------
// Node linear via tf32x3 tensor-core MMA (5 weight sets via gridDim.y).
// y = 0,1,2 (q,k,v) write __half output; y = 3,4 (skip,res) write fp32.
// ---------------------------------------------------------------------------
#define SA_STRIDE 36
#define SB_STRIDE 130
__global__ __launch_bounds__(256) void mma_linear5_kernel(
    const float* __restrict__ x,
    const float* __restrict__ Wq, const float* __restrict__ bq, __half* __restrict__ oq,
    const float* __restrict__ Wk, const float* __restrict__ bk, __half* __restrict__ ok,
    const float* __restrict__ Wv, const float* __restrict__ bv, __half* __restrict__ ov,
    const float* __restrict__ Ws, const float* __restrict__ bs, float* __restrict__ os,
    const float* __restrict__ Wr, const float* __restrict__ br, float* __restrict__ orr,
    int n) {
    extern __shared__ float2 dyn[];
    float2* sA = dyn;                     // 64*36
    float2* sB = dyn + 64 * SA_STRIDE;    // 32*130

    const float* W; const float* b;
    __half* outh = 0; float* outf = 0;
    switch (blockIdx.y) {
        case 0: W = Wq; b = bq; outh = oq; break;
        case 1: W = Wk; b = bk; outh = ok; break;
        case 2: W = Wv; b = bv; outh = ov; break;
        case 3: W = Ws; b = bs; outf = os; break;
        default: W = Wr; b = br; outf = orr; break;
    }
    const bool half_out = (blockIdx.y < 3);

    const int tid = threadIdx.x;
    const int wid = tid >> 5, lane = tid & 31;
    const int g = lane >> 2, t4 = lane & 3;
    const int wm = (wid & 1) * 32;
    const int wn = (wid >> 1) * 32;
    const int base = blockIdx.x * 64;

    float acc[2][4][4];
#pragma unroll
    for (int mi = 0; mi < 2; mi++)
#pragma unroll
        for (int ni = 0; ni < 4; ni++)
#pragma unroll
            for (int r = 0; r < 4; r++) acc[mi][ni][r] = 0.f;

    for (int kc = 0; kc < 4; kc++) {
#pragma unroll
        for (int t = 0; t < 2; t++) {
            int i = tid + t * 256;
            int row = i >> 3;
            int c4 = i & 7;
            int gr = base + row; if (gr >= n) gr = n - 1;
            const float4 xv = *(const float4*)(x + (size_t)gr * 128 + kc * 32 + c4 * 4);
            float2* dp = sA + row * SA_STRIDE + c4 * 4;
            dp[0] = tf32_split(xv.x);
            dp[1] = tf32_split(xv.y);
            dp[2] = tf32_split(xv.z);
            dp[3] = tf32_split(xv.w);
        }
#pragma unroll
        for (int t = 0; t < 4; t++) {
            int i = tid + t * 256;
            int row = i >> 5;
            int c4 = i & 31;
            const float4 wv = *(const float4*)(W + (size_t)(kc * 32 + row) * 128 + c4 * 4);
            float2* dp = sB + row * SB_STRIDE + c4 * 4;
            dp[0] = tf32_split(wv.x);
            dp[1] = tf32_split(wv.y);
            dp[2] = tf32_split(wv.z);
            dp[3] = tf32_split(wv.w);
        }
        __syncthreads();

#pragma unroll
        for (int k8 = 0; k8 < 4; k8++) {
            const int kk = k8 * 8;
            unsigned Ahi[2][4], Alo[2][4];
#pragma unroll
            for (int mi = 0; mi < 2; mi++) {
                const int r0 = wm + mi * 16 + g;
                const float2 a00 = sA[r0 * SA_STRIDE + kk + t4];
                const float2 a10 = sA[(r0 + 8) * SA_STRIDE + kk + t4];
                const float2 a01 = sA[r0 * SA_STRIDE + kk + t4 + 4];
                const float2 a11 = sA[(r0 + 8) * SA_STRIDE + kk + t4 + 4];
                Ahi[mi][0] = __float_as_uint(a00.x); Alo[mi][0] = __float_as_uint(a00.y);
                Ahi[mi][1] = __float_as_uint(a10.x); Alo[mi][1] = __float_as_uint(a10.y);
                Ahi[mi][2] = __float_as_uint(a01.x); Alo[mi][2] = __float_as_uint(a01.y);
                Ahi[mi][3] = __float_as_uint(a11.x); Alo[mi][3] = __float_as_uint(a11.y);
            }
            unsigned Bhi[4][2], Blo[4][2];
#pragma unroll
            for (int ni = 0; ni < 4; ni++) {
                const int col = wn + ni * 8 + g;
                const float2 b0 = sB[(kk + t4) * SB_STRIDE + col];
                const float2 b1 = sB[(kk + t4 + 4) * SB_STRIDE + col];
                Bhi[ni][0] = __float_as_uint(b0.x); Blo[ni][0] = __float_as_uint(b0.y);
                Bhi[ni][1] = __float_as_uint(b1.x); Blo[ni][1] = __float_as_uint(b1.y);
            }
#pragma unroll
            for (int mi = 0; mi < 2; mi++)
#pragma unroll
                for (int ni = 0; ni < 4; ni++) {
                    mma_tf32(acc[mi][ni], Ahi[mi], Bhi[ni]);
                    mma_tf32(acc[mi][ni], Ahi[mi], Blo[ni]);
                    mma_tf32(acc[mi][ni], Alo[mi], Bhi[ni]);
                }
        }
        __syncthreads();
    }

#pragma unroll
    for (int ni = 0; ni < 4; ni++) {
        const int col = wn + ni * 8 + 2 * t4;
        const float2 bb = *(const float2*)(b + col);
#pragma unroll
        for (int mi = 0; mi < 2; mi++) {
            const int node0 = base + wm + mi * 16 + g;
            if (node0 < n) {
                float2 o0 = make_float2(acc[mi][ni][0] + bb.x, acc[mi][ni][1] + bb.y);
                if (half_out)
                    *(__half2*)(outh + (size_t)node0 * 128 + col) = __float22half2_rn(o0);
                else
                    *(float2*)(outf + (size_t)node0 * 128 + col) = o0;
            }
            const int node1 = node0 + 8;
            if (node1 < n) {
                float2 o1 = make_float2(acc[mi][ni][2] + bb.x, acc[mi][ni][3] + bb.y);
                if (half_out)
                    *(__half2*)(outh + (size_t)node1 * 128 + col) = __float22half2_rn(o1);
                else
                    *(float2*)(outf + (size_t)node1 * 128 + col) = o1;
            }
        }
    }
}

// ---------------------------------------------------------------------------
// qe[n][d] = sum_c q[n][c] * We[d][c]   (128 -> 64); q input half, qe out half.
// ---------------------------------------------------------------------------
__global__ void qe_kernel(const __half* __restrict__ qh, const float* __restrict__ We,
                          __half* __restrict__ qeh, int n) {
    __shared__ float sWeT[128 * 64];
    __shared__ float sq[16 * 128];
    const int tid = threadIdx.x;       // 128
    for (int i = tid; i < 64 * 128; i += 128) {
        int d = i >> 7, c = i & 127;
        sWeT[c * 64 + d] = We[i];
    }
    __syncthreads();
    const int cg = tid & 15;
    const int ng = tid >> 4;

    for (int base = blockIdx.x * 16; base < n; base += gridDim.x * 16) {
        const int cnt = min(16, n - base);
        __syncthreads();
        for (int i = tid; i < cnt * 64; i += 128) {
            const __half2 hv = ((const __half2*)(qh + (size_t)base * 128))[i];
            const float2 f = __half22float2(hv);
            sq[i * 2] = f.x;
            sq[i * 2 + 1] = f.y;
        }
        __syncthreads();

        float acc[2][4] = {{0.f, 0.f, 0.f, 0.f}, {0.f, 0.f, 0.f, 0.f}};
#pragma unroll 2
        for (int c = 0; c < 128; c++) {
            const float4 w = *((const float4*)(sWeT + c * 64) + cg);
#pragma unroll
            for (int j = 0; j < 2; j++) {
                float xv = sq[(ng * 2 + j) * 128 + c];
                acc[j][0] = fmaf(xv, w.x, acc[j][0]);
                acc[j][1] = fmaf(xv, w.y, acc[j][1]);
                acc[j][2] = fmaf(xv, w.z, acc[j][2]);
                acc[j][3] = fmaf(xv, w.w, acc[j][3]);
            }
        }
#pragma unroll
        for (int j = 0; j < 2; j++) {
            const int node = ng * 2 + j;
            if (node < cnt) {
                const __half2 h0 = __floats2half2_rn(acc[j][0], acc[j][1]);
                const __half2 h1 = __floats2half2_rn(acc[j][2], acc[j][3]);
                uint2 pk;
                pk.x = *(const unsigned*)&h0;
                pk.y = *(const unsigned*)&h1;
                ((uint2*)(qeh + (size_t)(base + node) * 64))[cg] = pk;
            }
        }
    }
}

// ---------------------------------------------------------------------------
// gate[n] = sigmoid(x[n] . Wg + bg)
// ---------------------------------------------------------------------------
__global__ void gate_kernel(const float* __restrict__ x, const float* __restrict__ Wg,
                            const float* __restrict__ bg, float* __restrict__ gate, int n) {
    const int node = blockIdx.x * (blockDim.x >> 5) + (threadIdx.x >> 5);
    const int lane = threadIdx.x & 31;
    if (node >= n) return;
    const float4 a = ((const float4*)(x + (size_t)node * 128))[lane];
    const float4 w = ((const float4*)Wg)[lane];
    float s = a.x * w.x + a.y * w.y + a.z * w.z + a.w * w.w;
#pragma unroll
    for (int o = 16; o > 0; o >>= 1) s += __shfl_xor_sync(0xffffffffu, s, o);
    if (lane == 0) gate[node] = 1.f / (1.f + __expf(-(s + bg[0])));
}

// ---------------------------------------------------------------------------
// init: fast grid-stride uint4 zeroing of fp16 accumulators.
// aggVh: n*128 halves = n*16 uint4 ; sh: n*64 halves = n*8 uint4.
// ---------------------------------------------------------------------------
__global__ void init_kernel(uint4* __restrict__ aggV4, uint4* __restrict__ sagg4,
                            float* __restrict__ denom, int n) {
    const uint4 z = make_uint4(0u, 0u, 0u, 0u);
    const int stride = gridDim.x * blockDim.x;
    const int t = blockIdx.x * blockDim.x + threadIdx.x;
    for (int i = t; i < n * 16; i += stride) aggV4[i] = z;
    for (int i = t; i < n * 8; i += stride) sagg4[i] = z;
    for (int i = t; i < n; i += stride) denom[i] = 0.f;
}

// ---------------------------------------------------------------------------
// fp16x2 vector reductions (sm_90+) and helpers
// ---------------------------------------------------------------------------
__device__ __forceinline__ void red_add_v4_f16x2(__half* p, unsigned a, unsigned b,
                                                 unsigned c, unsigned d) {
    asm volatile("red.global.add.noftz.v4.f16x2 [%0], {%1, %2, %3, %4};"
                 :: "l"(p), "r"(a), "r"(b), "r"(c), "r"(d) : "memory");
}
__device__ __forceinline__ void red_add_v2_f16x2(__half* p, unsigned a, unsigned b) {
    asm volatile("red.global.add.noftz.v2.f16x2 [%0], {%1, %2};"
                 :: "l"(p), "r"(a), "r"(b) : "memory");
}
__device__ __forceinline__ unsigned scale_h2(unsigned vbits, float ex) {
    const float2 f = __half22float2(*(const __half2*)&vbits);
    const __half2 r = __floats2half2_rn(f.x * ex, f.y * ex);
    return *(const unsigned*)&r;
}
__device__ __forceinline__ float dot8h(uint4 a, uint4 b) {
    const float2 a0 = __half22float2(*(const __half2*)&a.x);
    const float2 a1 = __half22float2(*(const __half2*)&a.y);
    const float2 a2 = __half22float2(*(const __half2*)&a.z);
    const float2 a3 = __half22float2(*(const __half2*)&a.w);
    const float2 b0 = __half22float2(*(const __half2*)&b.x);
    const float2 b1 = __half22float2(*(const __half2*)&b.y);
    const float2 b2 = __half22float2(*(const __half2*)&b.z);
    const float2 b3 = __half22float2(*(const __half2*)&b.w);
    return a0.x * b0.x + a0.y * b0.y + a1.x * b1.x + a1.y * b1.y
         + a2.x * b2.x + a2.y * b2.y + a3.x * b3.x + a3.y * b3.y;
}

// ---------------------------------------------------------------------------
// Fused edge pass: 4 edges per warp, HALF-WARP per edge.
// Lanes 0-15 handle edge hw=0, lanes 16-31 edge hw=1 (two pairs: jA=hw, jB=2+hw).
// Each lane owns 8 consecutive dims (uint4 of halves) -> one warp LDG covers
// two edges; REDs use vector f16x2 (33 lane-RED-ops/edge vs 65 fp32).
// ---------------------------------------------------------------------------
__global__ __launch_bounds__(256) void edge_fused_kernel(
    const int* __restrict__ ei, const float* __restrict__ ea,
    const __half* __restrict__ qh, const __half* __restrict__ kh,
    const __half* __restrict__ qeh, const __half* __restrict__ vh,
    float* __restrict__ denom, __half* __restrict__ aggVh,
    __half* __restrict__ sh, int ecnt) {
    const int warp = blockIdx.x * (blockDim.x >> 5) + (threadIdx.x >> 5);
    const int lane = threadIdx.x & 31;
    const int e0 = warp * 4;
    if (e0 >= ecnt) return;
    const int m = min(4, ecnt - e0);
    const int hw = lane >> 4, l16 = lane & 15;

    // Lane-parallel index fetch: lanes 0-3 src, lanes 4-7 dst.
    int idx = 0;
    if (lane < 4) {
        if (lane < m) idx = ei[e0 + lane];
    } else if (lane < 8) {
        if (lane - 4 < m) idx = ei[ecnt + e0 + lane - 4];
    }
    int srcs[4], dsts[4];
#pragma unroll
    for (int j = 0; j < 4; j++) {
        srcs[j] = __shfl_sync(0xffffffffu, idx, j);
        dsts[j] = __shfl_sync(0xffffffffu, idx, 4 + j);
    }

    const int jA = hw, jB = 2 + hw;
    const int jAc = (jA < m) ? jA : 0;
    const int jBc = (jB < m) ? jB : 0;
    const int sA = srcs[jAc], dA = dsts[jAc];
    const int sB = srcs[jBc], dB = dsts[jBc];

    // ---- issue all gathers up front (each LDG covers 2 edges) ----
    const uint4 qA  = *(const uint4*)(qh  + (size_t)dA * 128 + l16 * 8);
    const uint4 kA  = *(const uint4*)(kh  + (size_t)sA * 128 + l16 * 8);
    const uint4 qB  = *(const uint4*)(qh  + (size_t)dB * 128 + l16 * 8);
    const uint4 kB  = *(const uint4*)(kh  + (size_t)sB * 128 + l16 * 8);
    const uint2 qeA = *(const uint2*)(qeh + (size_t)dA * 64 + l16 * 4);
    const uint2 qeB = *(const uint2*)(qeh + (size_t)dB * 64 + l16 * 4);
    const float4 eaA = *(const float4*)(ea + (size_t)(e0 + jAc) * 64 + l16 * 4);
    const float4 eaB = *(const float4*)(ea + (size_t)(e0 + jBc) * 64 + l16 * 4);
    const uint4 vA  = *(const uint4*)(vh  + (size_t)sA * 128 + l16 * 8);
    const uint4 vB  = *(const uint4*)(vh  + (size_t)sB * 128 + l16 * 8);

    // ---- per-lane score partials (q.k over 8 dims + qe.ea over 4 dims) ----
    const float2 qa0 = __half22float2(*(const __half2*)&qeA.x);
    const float2 qa1 = __half22float2(*(const __half2*)&qeA.y);
    const float2 qb0 = __half22float2(*(const __half2*)&qeB.x);
    const float2 qb1 = __half22float2(*(const __half2*)&qeB.y);
    float tA = dot8h(qA, kA) + qa0.x * eaA.x + qa0.y * eaA.y + qa1.x * eaA.z + qa1.y * eaA.w;
    float tB = dot8h(qB, kB) + qb0.x * eaB.x + qb0.y * eaB.y + qb1.x * eaB.z + qb1.y * eaB.w;

    // butterfly within half-warp (2 independent chains)
#pragma unroll
    for (int o = 8; o > 0; o >>= 1) {
        tA += __shfl_xor_sync(0xffffffffu, tA, o);
        tB += __shfl_xor_sync(0xffffffffu, tB, o);
    }
    const float SCL = 0.08838834764831845f;   // 1/sqrt(128)
    const float ex0 = __expf(__shfl_sync(0xffffffffu, tA, 0)  * SCL);
    const float ex1 = __expf(__shfl_sync(0xffffffffu, tA, 16) * SCL);
    const float ex2 = __expf(__shfl_sync(0xffffffffu, tB, 0)  * SCL);
    const float ex3 = __expf(__shfl_sync(0xffffffffu, tB, 16) * SCL);
    const float exA = hw ? ex1 : ex0;
    const float exB = hw ? ex3 : ex2;

    // ---- vector fp16 reductions (pair A: edges 0/1) ----
    if (jA < m) {
        red_add_v4_f16x2(aggVh + (size_t)dA * 128 + l16 * 8,
                         scale_h2(vA.x, exA), scale_h2(vA.y, exA),
                         scale_h2(vA.z, exA), scale_h2(vA.w, exA));
        const __half2 s0 = __floats2half2_rn(exA * eaA.x, exA * eaA.y);
        const __half2 s1 = __floats2half2_rn(exA * eaA.z, exA * eaA.w);
        red_add_v2_f16x2(sh + (size_t)dA * 64 + l16 * 4,
                         *(const unsigned*)&s0, *(const unsigned*)&s1);
        if (l16 == 0) atomicAdd(&denom[dA], exA);
    }
    // ---- pair B: edges 2/3 ----
    if (jB < m) {
        red_add_v4_f16x2(aggVh + (size_t)dB * 128 + l16 * 8,
                         scale_h2(vB.x, exB), scale_h2(vB.y, exB),
                         scale_h2(vB.z, exB), scale_h2(vB.w, exB));
        const __half2 s0 = __floats2half2_rn(exB * eaB.x, exB * eaB.y);
        const __half2 s1 = __floats2half2_rn(exB * eaB.z, exB * eaB.w);
        red_add_v2_f16x2(sh + (size_t)dB * 64 + l16 * 4,
                         *(const unsigned*)&s0, *(const unsigned*)&s1);
        if (l16 == 0) atomicAdd(&denom[dB], exB);
    }
}

// ---------------------------------------------------------------------------
// Final fused: h = (aggV + s @ We)/denom + skip ; LayerNorm ; relu ; gated res.
// aggV/sagg are fp16 now.
// ---------------------------------------------------------------------------
__global__ void final_kernel(const __half* __restrict__ aggVh, const __half* __restrict__ sh,
                             const float* __restrict__ We, const float* __restrict__ skip,
                             const float* __restrict__ denom,
                             const float* __restrict__ res, const float* __restrict__ gate,
                             const float* __restrict__ ln_g, const float* __restrict__ ln_b,
                             float* __restrict__ out, int n) {
    __shared__ float sWe[64 * 128];
    __shared__ float ssm[2][64];
    __shared__ float red[2][4];
    const int tid = threadIdx.x;      // 256
    for (int i = tid; i < 64 * 128; i += 256) sWe[i] = We[i];
    const int grp  = tid >> 7;
    const int c    = tid & 127;
    const int wig  = (tid & 127) >> 5;
    const int lane = tid & 31;
    const float lg = ln_g[c], lb = ln_b[c];
    __syncthreads();

    for (int base = blockIdx.x * 2; base < n; base += gridDim.x * 2) {
        const bool valid = (base + grp) < n;
        const int nn = valid ? (base + grp) : (n - 1);
        __syncthreads();
        if (c < 64) ssm[grp][c] = __half2float(sh[(size_t)nn * 64 + c]);
        __syncthreads();

        float hraw = __half2float(aggVh[(size_t)nn * 128 + c]);
#pragma unroll 4
        for (int d = 0; d < 64; d++) hraw = fmaf(ssm[grp][d], sWe[d * 128 + c], hraw);
        const float dn = denom[nn];
        const float inv = (dn > 0.f) ? (1.f / dn) : 0.f;
        float h = hraw * inv + skip[(size_t)nn * 128 + c];

        float t = h;
#pragma unroll
        for (int o = 16; o > 0; o >>= 1) t += __shfl_xor_sync(0xffffffffu, t, o);
        if (lane == 0) red[grp][wig] = t;
        __syncthreads();
        const float mu = (red[grp][0] + red[grp][1] + red[grp][2] + red[grp][3]) * (1.f / 128.f);
        __syncthreads();

        const float dv = h - mu;
        t = dv * dv;
#pragma unroll
        for (int o = 16; o > 0; o >>= 1) t += __shfl_xor_sync(0xffffffffu, t, o);
        if (lane == 0) red[grp][wig] = t;
        __syncthreads();
        const float var = (red[grp][0] + red[grp][1] + red[grp][2] + red[grp][3]) * (1.f / 128.f);

        float y = dv * rsqrtf(var + 1e-5f) * lg + lb;
        y = fmaxf(y, 0.f);
        const float g = gate[nn];
        const float ov = g * y + (1.f - g) * res[(size_t)nn * 128 + c];
        if (valid) out[(size_t)(base + grp) * 128 + c] = ov;
    }
}

// ---------------------------------------------------------------------------
extern "C" void kernel_launch(void* const* d_in, const int* in_sizes, int n_in,
                              void* d_out, int out_size) {
    const float* x     = (const float*)d_in[0];
    const int*   ei    = (const int*)  d_in[1];
    const float* ea    = (const float*)d_in[2];
    const float* Wq    = (const float*)d_in[3];
    const float* bq    = (const float*)d_in[4];
    const float* Wk    = (const float*)d_in[5];
    const float* bk    = (const float*)d_in[6];
    const float* Wv    = (const float*)d_in[7];
    const float* bv    = (const float*)d_in[8];
    const float* We    = (const float*)d_in[9];
    const float* Wskip = (const float*)d_in[10];
    const float* bskip = (const float*)d_in[11];
    const float* ln_g  = (const float*)d_in[12];
    const float* ln_b  = (const float*)d_in[13];
    const float* Wres  = (const float*)d_in[14];
    const float* bres  = (const float*)d_in[15];
    const float* Wgate = (const float*)d_in[16];
    const float* bgate = (const float*)d_in[17];
    float* out = (float*)d_out;

    int n = in_sizes[0] / 128;
    int ecnt = in_sizes[1] / 2;
    if (n > N_MAX) n = N_MAX;
    if (ecnt > E_MAX) ecnt = E_MAX;

    __half *qhp, *khp, *vhp, *qehp, *aggVh, *shp;
    float *skip, *res, *gate, *denom;
    cudaGetSymbolAddress((void**)&qhp,   g_qh);
    cudaGetSymbolAddress((void**)&khp,   g_kh);
    cudaGetSymbolAddress((void**)&vhp,   g_vh);
    cudaGetSymbolAddress((void**)&qehp,  g_qeh);
    cudaGetSymbolAddress((void**)&skip,  g_skip);
    cudaGetSymbolAddress((void**)&res,   g_res);
    cudaGetSymbolAddress((void**)&shp,   g_sh);
    cudaGetSymbolAddress((void**)&aggVh, g_aggVh);
    cudaGetSymbolAddress((void**)&gate,  g_gate);
    cudaGetSymbolAddress((void**)&denom, g_denom);

    const int mma_smem = (64 * SA_STRIDE + 32 * SB_STRIDE) * (int)sizeof(float2);
    cudaFuncSetAttribute(mma_linear5_kernel, cudaFuncAttributeMaxDynamicSharedMemorySize, mma_smem);

    // All 5 node projections in one launch (q/k/v -> fp16, skip/res -> fp32)
    dim3 mma_grid((n + 63) / 64, 5, 1);
    mma_linear5_kernel<<<mma_grid, 256, mma_smem>>>(
        x, Wq, bq, qhp, Wk, bk, khp, Wv, bv, vhp, Wskip, bskip, skip, Wres, bres, res, n);

    qe_kernel<<<740, 128>>>(qhp, We, qehp, n);
    gate_kernel<<<(n + 7) / 8, 256>>>(x, Wgate, bgate, gate, n);

    // init fp16 accumulators (grid-stride vectorized)
    init_kernel<<<592, 256>>>((uint4*)aggVh, (uint4*)shp, denom, n);

    // Single fused edge pass, 4 edges per warp, half-warp per edge
    const int nwarps = (ecnt + 3) / 4;
    edge_fused_kernel<<<(nwarps + 7) / 8, 256>>>(ei, ea, qhp, khp, qehp, vhp,
                                                 denom, aggVh, shp, ecnt);

    // Final fused epilogue
    final_kernel<<<740, 256>>>(aggVh, shp, We, skip, denom, res, gate, ln_g, ln_b, out, n);
}